// round 5
// baseline (speedup 1.0000x reference)
#include <cuda_runtime.h>
#include <cuda_fp16.h>
#include <mma.h>
#include <cstdint>

using namespace nvcuda;

// ---------------------------------------------------------------------------
// Problem constants
// ---------------------------------------------------------------------------
static constexpr int M = 4096;      // tokens
static constexpr int K = 4096;      // in_features
static constexpr int N = 11008;     // out_features
static constexpr int KP = K / 8;    // packed qweight rows

// GEMM tiling
static constexpr int BM = 256;
static constexpr int BN = 128;
static constexpr int BK = 64;
static constexpr int STAGES = 4;
static constexpr int NIT = K / BK;          // 64
static constexpr int PAD = 8;               // halves
static constexpr int LDS_T = BK + PAD;      // 72 halves = 144B row stride
static constexpr int A_HALFS = BM * LDS_T;            // 18432
static constexpr int STAGE_HALFS = (BM + BN) * LDS_T; // 27648 halves = 55296B
static constexpr int SMEM_BYTES = STAGES * STAGE_HALFS * 2;  // 221184

// fp16 scratch (static __device__ -- no allocation)
__device__ __half g_Wt[(size_t)N * K];   // W transposed: [N, K]
__device__ __half g_Xh[(size_t)M * K];   // x as fp16:    [M, K]

// ---------------------------------------------------------------------------
__device__ __forceinline__ uint32_t smem_u32(const void* p) {
    uint32_t a;
    asm("{ .reg .u64 t; cvta.to.shared.u64 t, %1; cvt.u32.u64 %0, t; }" : "=r"(a) : "l"(p));
    return a;
}
__device__ __forceinline__ void cp_async16(uint32_t dst, const void* src) {
    asm volatile("cp.async.cg.shared.global [%0], [%1], 16;" :: "r"(dst), "l"(src) : "memory");
}
__device__ __forceinline__ void cp_commit() {
    asm volatile("cp.async.commit_group;" ::: "memory");
}
__device__ __forceinline__ void cp_wait2() {
    asm volatile("cp.async.wait_group 2;" ::: "memory");
}
__device__ __forceinline__ void cp_wait0() {
    asm volatile("cp.async.wait_group 0;" ::: "memory");
}

// ---------------------------------------------------------------------------
// Pre-pass 1: x f32 -> g_Xh fp16
// ---------------------------------------------------------------------------
__global__ void convert_x_kernel(const float* __restrict__ x) {
    size_t base = ((size_t)blockIdx.x * blockDim.x + threadIdx.x) * 8;
    if (base >= (size_t)M * K) return;
    float4 a = *(const float4*)&x[base];
    float4 b = *(const float4*)&x[base + 4];
    __half2 h[4];
    h[0] = __floats2half2_rn(a.x, a.y);
    h[1] = __floats2half2_rn(a.z, a.w);
    h[2] = __floats2half2_rn(b.x, b.y);
    h[3] = __floats2half2_rn(b.z, b.w);
    *(uint4*)&g_Xh[base] = *(uint4*)h;
}

// ---------------------------------------------------------------------------
// Pre-pass 2: dequant to transposed g_Wt [N, K] fp16 (K-major rows).
// ---------------------------------------------------------------------------
__global__ void dequant_kernel(const int* __restrict__ qweight,
                               const int* __restrict__ qzeros,
                               const float* __restrict__ scales,
                               const int* __restrict__ g_idx) {
    int n  = blockIdx.x * 32 + (threadIdx.x >> 3);
    int kk = blockIdx.y * 8  + (threadIdx.x & 7);
    if (n >= N) return;

    int   g    = g_idx[kk * 8];
    int   qw   = qweight[(size_t)kk * N + n];
    int   qz   = qzeros[(size_t)g * (N / 8) + (n >> 3)];
    int   zero = ((qz >> ((n & 7) * 4)) & 15) + 1;
    float s    = scales[(size_t)g * N + n];

    __half h[8];
#pragma unroll
    for (int i = 0; i < 8; i++) {
        int w = ((qw >> (4 * i)) & 15) - zero;
        h[i] = __float2half(s * (float)w);
    }
    *(uint4*)&g_Wt[(size_t)n * K + kk * 8] = *(uint4*)h;
}

// ---------------------------------------------------------------------------
// GEMM: C[M,N] = g_Xh[M,K] @ g_Wt[N,K]^T + bias.
// 256x128 CTA tile, BK=64, 4-stage cp.async pipeline, 8 warps 4(M)x2(N),
// warp tile 64x64 (4x4 wmma frags). B consumed col_major from [N,K].
// ---------------------------------------------------------------------------
__global__ __launch_bounds__(256, 1)
void gemm_kernel(const float* __restrict__ bias, float* __restrict__ C) {
    extern __shared__ __half smem[];
    const uint32_t sbase = smem_u32(smem);

    const int tid  = threadIdx.x;
    const int warp = tid >> 5;
    const int lane = tid & 31;
    const int wm   = warp >> 1;   // 0..3 : warp row (64 rows each)
    const int wn   = warp & 1;    // 0..1 : warp col (64 cols each)

    const int bm = blockIdx.y * BM;
    const int bn = blockIdx.x * BN;

    // cp.async mapping: 12 x 16B chunks per thread per stage.
    // Rows have 64 halves = 8 chunks. A: 256 rows = 2048 chunks (l=0..7),
    // B: 128 rows = 1024 chunks (l=8..11).
    const int ra = tid >> 3;            // 0..31 (A row base; +32 per l)
    const int c0 = tid & 7;             // 0..7  chunk-in-row
    const __half* gA = g_Xh + (size_t)(bm + ra) * K + c0 * 8;
    const __half* gB = g_Wt + (size_t)(bn + ra) * K + c0 * 8;
    const uint32_t dA = (uint32_t)(ra * LDS_T + c0 * 8) * 2;
    const uint32_t dB = (uint32_t)((A_HALFS + ra * LDS_T) + c0 * 8) * 2;

    wmma::fragment<wmma::accumulator, 16, 16, 16, float> acc[4][4];
#pragma unroll
    for (int i = 0; i < 4; i++)
#pragma unroll
        for (int j = 0; j < 4; j++)
            wmma::fill_fragment(acc[i][j], 0.0f);

    // prologue: issue stages 0..2
#pragma unroll
    for (int s = 0; s < STAGES - 1; s++) {
        const uint32_t st = sbase + (uint32_t)(s * STAGE_HALFS) * 2;
        const size_t ko = (size_t)s * BK;
#pragma unroll
        for (int l = 0; l < 8; l++)
            cp_async16(st + dA + l * 32 * LDS_T * 2, gA + (size_t)l * 32 * K + ko);
#pragma unroll
        for (int l = 0; l < 4; l++)
            cp_async16(st + dB + l * 32 * LDS_T * 2, gB + (size_t)l * 32 * K + ko);
        cp_commit();
    }

    for (int i = 0; i < NIT; i++) {
        cp_wait2();
        __syncthreads();

        const int s = i & (STAGES - 1);
        const __half* As = smem + s * STAGE_HALFS;
        const __half* Bs = As + A_HALFS;

#pragma unroll
        for (int kk = 0; kk < BK; kk += 16) {
            wmma::fragment<wmma::matrix_a, 16, 16, 16, __half, wmma::row_major> a[4];
            wmma::fragment<wmma::matrix_b, 16, 16, 16, __half, wmma::col_major> b[4];
#pragma unroll
            for (int ii = 0; ii < 4; ii++)
                wmma::load_matrix_sync(a[ii], As + (wm * 64 + ii * 16) * LDS_T + kk, LDS_T);
#pragma unroll
            for (int j = 0; j < 4; j++)
                wmma::load_matrix_sync(b[j], Bs + (wn * 64 + j * 16) * LDS_T + kk, LDS_T);
#pragma unroll
            for (int ii = 0; ii < 4; ii++)
#pragma unroll
                for (int j = 0; j < 4; j++)
                    wmma::mma_sync(acc[ii][j], a[ii], b[j], acc[ii][j]);
        }
        __syncthreads();

        const int p = i + STAGES - 1;
        if (p < NIT) {
            const uint32_t st = sbase + (uint32_t)((p & (STAGES - 1)) * STAGE_HALFS) * 2;
            const size_t ko = (size_t)p * BK;
#pragma unroll
            for (int l = 0; l < 8; l++)
                cp_async16(st + dA + l * 32 * LDS_T * 2, gA + (size_t)l * 32 * K + ko);
#pragma unroll
            for (int l = 0; l < 4; l++)
                cp_async16(st + dB + l * 32 * LDS_T * 2, gB + (size_t)l * 32 * K + ko);
        }
        cp_commit();
    }
    cp_wait0();
    __syncthreads();

    // Epilogue: stage each 16x16 acc through smem, add bias, store f32.
    float* st = (float*)smem + warp * 256;
    const int row     = lane >> 1;
    const int colbase = (lane & 1) * 8;
#pragma unroll
    for (int i = 0; i < 4; i++) {
#pragma unroll
        for (int j = 0; j < 4; j++) {
            wmma::store_matrix_sync(st, acc[i][j], 16, wmma::mem_row_major);
            __syncwarp();
            int gm = bm + wm * 64 + i * 16 + row;
            int gn = bn + wn * 64 + j * 16 + colbase;
            float* cptr = &C[(size_t)gm * N + gn];
            const float* sp = &st[row * 16 + colbase];
            float4 v0, v1;
            v0.x = sp[0] + bias[gn + 0];
            v0.y = sp[1] + bias[gn + 1];
            v0.z = sp[2] + bias[gn + 2];
            v0.w = sp[3] + bias[gn + 3];
            v1.x = sp[4] + bias[gn + 4];
            v1.y = sp[5] + bias[gn + 5];
            v1.z = sp[6] + bias[gn + 6];
            v1.w = sp[7] + bias[gn + 7];
            *(float4*)cptr = v0;
            *(float4*)(cptr + 4) = v1;
            __syncwarp();
        }
    }
}

// ---------------------------------------------------------------------------
extern "C" void kernel_launch(void* const* d_in, const int* in_sizes, int n_in,
                              void* d_out, int out_size) {
    const float* x       = (const float*)d_in[0];
    const int*   qweight = (const int*)d_in[1];
    const int*   qzeros  = (const int*)d_in[2];
    const float* scales  = (const float*)d_in[3];
    const int*   g_idx   = (const int*)d_in[4];
    const float* bias    = (const float*)d_in[5];
    float*       out     = (float*)d_out;

    cudaFuncSetAttribute(gemm_kernel,
                         cudaFuncAttributeMaxDynamicSharedMemorySize, SMEM_BYTES);

    convert_x_kernel<<<((size_t)M * K / 8 + 255) / 256, 256>>>(x);

    dim3 dq_grid(N / 32, KP / 8);
    dequant_kernel<<<dq_grid, 256>>>(qweight, qzeros, scales, g_idx);

    dim3 gemm_grid(N / BN, M / BM);   // 86 x 16
    gemm_kernel<<<gemm_grid, 256, SMEM_BYTES>>>(bias, out);
}

// round 6
// speedup vs baseline: 1.1378x; 1.1378x over previous
#include <cuda_runtime.h>
#include <cuda_fp16.h>
#include <cstdint>

// ---------------------------------------------------------------------------
// Problem constants
// ---------------------------------------------------------------------------
static constexpr int M = 4096;      // tokens
static constexpr int K = 4096;      // in_features
static constexpr int N = 11008;     // out_features
static constexpr int KP = K / 8;    // packed qweight rows

// GEMM tiling
static constexpr int BM = 128;
static constexpr int BN = 128;
static constexpr int BK = 32;
static constexpr int STAGES = 4;
static constexpr int NIT = K / BK;          // 128
static constexpr int LDS_T = 40;            // halves: 32 + 8 pad = 80B stride
static constexpr int A_HALFS = BM * LDS_T;  // 5120
static constexpr int STAGE_HALFS = (BM + BN) * LDS_T;  // 10240
static constexpr int STAGE_BYTES = STAGE_HALFS * 2;    // 20480
static constexpr int SMEM_BYTES = STAGES * STAGE_BYTES; // 81920

// fp16 scratch (static __device__ -- no allocation)
__device__ __half g_Wt[(size_t)N * K];   // W transposed: [N, K]
__device__ __half g_Xh[(size_t)M * K];   // x as fp16:    [M, K]

// ---------------------------------------------------------------------------
__device__ __forceinline__ uint32_t smem_u32(const void* p) {
    uint32_t a;
    asm("{ .reg .u64 t; cvta.to.shared.u64 t, %1; cvt.u32.u64 %0, t; }" : "=r"(a) : "l"(p));
    return a;
}
__device__ __forceinline__ void cp_async16(uint32_t dst, const void* src) {
    asm volatile("cp.async.cg.shared.global [%0], [%1], 16;" :: "r"(dst), "l"(src) : "memory");
}
__device__ __forceinline__ void cp_commit() {
    asm volatile("cp.async.commit_group;" ::: "memory");
}
__device__ __forceinline__ void cp_wait2() {
    asm volatile("cp.async.wait_group 2;" ::: "memory");
}
__device__ __forceinline__ void cp_wait0() {
    asm volatile("cp.async.wait_group 0;" ::: "memory");
}
__device__ __forceinline__ void ldsm_x4(uint32_t* r, uint32_t addr) {
    asm volatile("ldmatrix.sync.aligned.m8n8.x4.shared.b16 {%0,%1,%2,%3}, [%4];"
                 : "=r"(r[0]), "=r"(r[1]), "=r"(r[2]), "=r"(r[3]) : "r"(addr));
}
__device__ __forceinline__ void mma16816(float* c, const uint32_t* a, const uint32_t* b) {
    asm volatile("mma.sync.aligned.m16n8k16.row.col.f32.f16.f16.f32 "
                 "{%0,%1,%2,%3}, {%4,%5,%6,%7}, {%8,%9}, {%0,%1,%2,%3};"
                 : "+f"(c[0]), "+f"(c[1]), "+f"(c[2]), "+f"(c[3])
                 : "r"(a[0]), "r"(a[1]), "r"(a[2]), "r"(a[3]), "r"(b[0]), "r"(b[1]));
}

// ---------------------------------------------------------------------------
// Fused prep: blocks [0, 8192): x f32 -> g_Xh fp16 ; rest: dequant -> g_Wt
// ---------------------------------------------------------------------------
static constexpr int CONV_BLOCKS = (int)((size_t)M * K / 8 / 256);  // 8192
__global__ void prep_kernel(const float* __restrict__ x,
                            const int* __restrict__ qweight,
                            const int* __restrict__ qzeros,
                            const float* __restrict__ scales,
                            const int* __restrict__ g_idx) {
    if (blockIdx.x < CONV_BLOCKS) {
        size_t base = ((size_t)blockIdx.x * 256 + threadIdx.x) * 8;
        float4 a = *(const float4*)&x[base];
        float4 b = *(const float4*)&x[base + 4];
        __half2 h[4];
        h[0] = __floats2half2_rn(a.x, a.y);
        h[1] = __floats2half2_rn(a.z, a.w);
        h[2] = __floats2half2_rn(b.x, b.y);
        h[3] = __floats2half2_rn(b.z, b.w);
        *(uint4*)&g_Xh[base] = *(uint4*)h;
    } else {
        int dq = blockIdx.x - CONV_BLOCKS;
        int bx = dq % (N / 32);
        int by = dq / (N / 32);
        int n  = bx * 32 + (threadIdx.x >> 3);
        int kk = by * 8  + (threadIdx.x & 7);

        int   g    = g_idx[kk * 8];
        int   qw   = qweight[(size_t)kk * N + n];
        int   qz   = qzeros[(size_t)g * (N / 8) + (n >> 3)];
        int   zero = ((qz >> ((n & 7) * 4)) & 15) + 1;
        float s    = scales[(size_t)g * N + n];

        __half h[8];
#pragma unroll
        for (int i = 0; i < 8; i++) {
            int w = ((qw >> (4 * i)) & 15) - zero;
            h[i] = __float2half(s * (float)w);
        }
        *(uint4*)&g_Wt[(size_t)n * K + kk * 8] = *(uint4*)h;
    }
}

// ---------------------------------------------------------------------------
// GEMM: C[M,N] = g_Xh[M,K] @ g_Wt[N,K]^T + bias.
// 128x128 CTA, BK=32, 4-stage cp.async, 128 threads = 4 warps (2x2),
// warp tile 64x64 via raw mma.sync m16n8k16 + ldmatrix.x4 (non-trans for B).
// ---------------------------------------------------------------------------
__global__ __launch_bounds__(128, 2)
void gemm_kernel(const float* __restrict__ bias, float* __restrict__ C) {
    extern __shared__ __half smem[];
    const uint32_t sbase = smem_u32(smem);

    const int tid  = threadIdx.x;
    const int warp = tid >> 5;
    const int lane = tid & 31;
    const int wm   = (warp >> 1) * 64;   // warp M offset within CTA
    const int wn   = (warp & 1) * 64;    // warp N offset within CTA

    const int bm = blockIdx.y * BM;
    const int bn = blockIdx.x * BN;

    // ---- cp.async mapping: 1024 x 16B chunks/stage, 8 per thread ----
    const int r0 = tid >> 2;            // 0..31
    const int c0 = tid & 3;             // chunk in 64B row
    const __half* gA = g_Xh + (size_t)(bm + r0) * K + c0 * 8;
    const __half* gB = g_Wt + (size_t)(bn + r0) * K + c0 * 8;
    const uint32_t dA = (uint32_t)(r0 * LDS_T + c0 * 8) * 2;
    const uint32_t dB = dA + A_HALFS * 2;

    // ---- ldmatrix lane address components (within a stage, in bytes) ----
    // A, m-tile mi, k-slice ks: row = wm + mi*16 + (lane&15); col = ks + (lane>>4)*8
    const uint32_t aRow = (uint32_t)(wm + (lane & 15));
    const uint32_t aColX = (uint32_t)((lane >> 4) * 8);
    const uint32_t aBase = sbase + (aRow * LDS_T + aColX) * 2;
    // B, n-pair nj (16 cols), k-slice ks:
    // row = wn + nj*16 + (lane&7) + ((lane>>4)<<3); col = ks + ((lane>>3)&1)*8
    const uint32_t bRow = (uint32_t)(wn + (lane & 7) + ((lane >> 4) << 3));
    const uint32_t bColX = (uint32_t)(((lane >> 3) & 1) * 8);
    const uint32_t bBase = sbase + A_HALFS * 2 + (bRow * LDS_T + bColX) * 2;

    float acc[4][8][4];
#pragma unroll
    for (int i = 0; i < 4; i++)
#pragma unroll
        for (int j = 0; j < 8; j++)
#pragma unroll
            for (int t = 0; t < 4; t++)
                acc[i][j][t] = 0.0f;

    // ---- prologue: stages 0..2 ----
#pragma unroll
    for (int s = 0; s < STAGES - 1; s++) {
        const uint32_t st = sbase + (uint32_t)s * STAGE_BYTES;
        const size_t ko = (size_t)s * BK;
#pragma unroll
        for (int l = 0; l < 4; l++) {
            cp_async16(st + dA + l * 32 * LDS_T * 2, gA + (size_t)l * 32 * K + ko);
            cp_async16(st + dB + l * 32 * LDS_T * 2, gB + (size_t)l * 32 * K + ko);
        }
        cp_commit();
    }

    for (int i = 0; i < NIT; i++) {
        cp_wait2();
        __syncthreads();

        const uint32_t so = (uint32_t)(i & (STAGES - 1)) * STAGE_BYTES;

#pragma unroll
        for (int ks = 0; ks < BK; ks += 16) {
            uint32_t a[4][4], b[4][4];
#pragma unroll
            for (int mi = 0; mi < 4; mi++)
                ldsm_x4(a[mi], aBase + so + (mi * 16 * LDS_T + ks) * 2);
#pragma unroll
            for (int nj = 0; nj < 4; nj++)
                ldsm_x4(b[nj], bBase + so + (nj * 16 * LDS_T + ks) * 2);
#pragma unroll
            for (int mi = 0; mi < 4; mi++) {
#pragma unroll
                for (int nj = 0; nj < 4; nj++) {
                    mma16816(acc[mi][nj * 2 + 0], a[mi], &b[nj][0]);
                    mma16816(acc[mi][nj * 2 + 1], a[mi], &b[nj][2]);
                }
            }
        }

        const int p = i + STAGES - 1;
        if (p < NIT) {
            const uint32_t st = sbase + (uint32_t)(p & (STAGES - 1)) * STAGE_BYTES;
            const size_t ko = (size_t)p * BK;
#pragma unroll
            for (int l = 0; l < 4; l++) {
                cp_async16(st + dA + l * 32 * LDS_T * 2, gA + (size_t)l * 32 * K + ko);
                cp_async16(st + dB + l * 32 * LDS_T * 2, gB + (size_t)l * 32 * K + ko);
            }
        }
        cp_commit();
    }
    cp_wait0();

    // ---- epilogue: direct register -> global, fused bias ----
    // acc layout (m16n8): lane holds (row l/4, col 2(l%4)) and (row l/4+8, same col)
    const int erow = lane >> 2;
    const int ecol = (lane & 3) * 2;
    float2 bb[8];
#pragma unroll
    for (int nj = 0; nj < 8; nj++)
        bb[nj] = *(const float2*)&bias[bn + wn + nj * 8 + ecol];

#pragma unroll
    for (int mi = 0; mi < 4; mi++) {
        const int gm0 = bm + wm + mi * 16 + erow;
#pragma unroll
        for (int nj = 0; nj < 8; nj++) {
            const int gn = bn + wn + nj * 8 + ecol;
            float2 v0, v1;
            v0.x = acc[mi][nj][0] + bb[nj].x;
            v0.y = acc[mi][nj][1] + bb[nj].y;
            v1.x = acc[mi][nj][2] + bb[nj].x;
            v1.y = acc[mi][nj][3] + bb[nj].y;
            *(float2*)&C[(size_t)gm0 * N + gn] = v0;
            *(float2*)&C[(size_t)(gm0 + 8) * N + gn] = v1;
        }
    }
}

// ---------------------------------------------------------------------------
extern "C" void kernel_launch(void* const* d_in, const int* in_sizes, int n_in,
                              void* d_out, int out_size) {
    const float* x       = (const float*)d_in[0];
    const int*   qweight = (const int*)d_in[1];
    const int*   qzeros  = (const int*)d_in[2];
    const float* scales  = (const float*)d_in[3];
    const int*   g_idx   = (const int*)d_in[4];
    const float* bias    = (const float*)d_in[5];
    float*       out     = (float*)d_out;

    cudaFuncSetAttribute(gemm_kernel,
                         cudaFuncAttributeMaxDynamicSharedMemorySize, SMEM_BYTES);

    int prep_blocks = CONV_BLOCKS + (N / 32) * (KP / 8);
    prep_kernel<<<prep_blocks, 256>>>(x, qweight, qzeros, scales, g_idx);

    dim3 gemm_grid(N / BN, M / BM);   // 86 x 32
    gemm_kernel<<<gemm_grid, 128, SMEM_BYTES>>>(bias, out);
}

// round 7
// speedup vs baseline: 1.2107x; 1.0640x over previous
#include <cuda_runtime.h>
#include <cuda_fp16.h>
#include <cstdint>

// ---------------------------------------------------------------------------
// Problem constants
// ---------------------------------------------------------------------------
static constexpr int M = 4096;      // tokens
static constexpr int K = 4096;      // in_features
static constexpr int N = 11008;     // out_features
static constexpr int KP = K / 8;    // packed qweight rows

// GEMM tiling
static constexpr int BM = 128;
static constexpr int BN = 128;
static constexpr int BK = 64;
static constexpr int STAGES = 3;
static constexpr int NIT = K / BK;          // 64
static constexpr int LDS_T = 72;            // halves: 64 + 8 pad = 144B stride
static constexpr int A_HALFS = BM * LDS_T;  // 9216
static constexpr int STAGE_HALFS = (BM + BN) * LDS_T;  // 18432
static constexpr int STAGE_BYTES = STAGE_HALFS * 2;    // 36864
static constexpr int SMEM_BYTES = STAGES * STAGE_BYTES; // 110592

// fp16 scratch (static __device__ -- no allocation)
__device__ __half g_Wt[(size_t)N * K];   // W transposed: [N, K]
__device__ __half g_Xh[(size_t)M * K];   // x as fp16:    [M, K]

// ---------------------------------------------------------------------------
__device__ __forceinline__ uint32_t smem_u32(const void* p) {
    uint32_t a;
    asm("{ .reg .u64 t; cvta.to.shared.u64 t, %1; cvt.u32.u64 %0, t; }" : "=r"(a) : "l"(p));
    return a;
}
__device__ __forceinline__ void cp_async16(uint32_t dst, const void* src) {
    asm volatile("cp.async.cg.shared.global [%0], [%1], 16;" :: "r"(dst), "l"(src) : "memory");
}
__device__ __forceinline__ void cp_commit() {
    asm volatile("cp.async.commit_group;" ::: "memory");
}
__device__ __forceinline__ void cp_wait1() {
    asm volatile("cp.async.wait_group 1;" ::: "memory");
}
__device__ __forceinline__ void cp_wait0() {
    asm volatile("cp.async.wait_group 0;" ::: "memory");
}
__device__ __forceinline__ void ldsm_x4(uint32_t* r, uint32_t addr) {
    asm volatile("ldmatrix.sync.aligned.m8n8.x4.shared.b16 {%0,%1,%2,%3}, [%4];"
                 : "=r"(r[0]), "=r"(r[1]), "=r"(r[2]), "=r"(r[3]) : "r"(addr));
}
__device__ __forceinline__ void mma16816(float* c, const uint32_t* a, const uint32_t* b) {
    asm volatile("mma.sync.aligned.m16n8k16.row.col.f32.f16.f16.f32 "
                 "{%0,%1,%2,%3}, {%4,%5,%6,%7}, {%8,%9}, {%0,%1,%2,%3};"
                 : "+f"(c[0]), "+f"(c[1]), "+f"(c[2]), "+f"(c[3])
                 : "r"(a[0]), "r"(a[1]), "r"(a[2]), "r"(a[3]), "r"(b[0]), "r"(b[1]));
}

// ---------------------------------------------------------------------------
// Fused prep: blocks [0, 8192): x f32 -> g_Xh fp16 ; rest: dequant -> g_Wt
// ---------------------------------------------------------------------------
static constexpr int CONV_BLOCKS = (int)((size_t)M * K / 8 / 256);  // 8192
__global__ void prep_kernel(const float* __restrict__ x,
                            const int* __restrict__ qweight,
                            const int* __restrict__ qzeros,
                            const float* __restrict__ scales,
                            const int* __restrict__ g_idx) {
    if (blockIdx.x < CONV_BLOCKS) {
        size_t base = ((size_t)blockIdx.x * 256 + threadIdx.x) * 8;
        float4 a = *(const float4*)&x[base];
        float4 b = *(const float4*)&x[base + 4];
        __half2 h[4];
        h[0] = __floats2half2_rn(a.x, a.y);
        h[1] = __floats2half2_rn(a.z, a.w);
        h[2] = __floats2half2_rn(b.x, b.y);
        h[3] = __floats2half2_rn(b.z, b.w);
        *(uint4*)&g_Xh[base] = *(uint4*)h;
    } else {
        int dq = blockIdx.x - CONV_BLOCKS;
        int bx = dq % (N / 32);
        int by = dq / (N / 32);
        int n  = bx * 32 + (threadIdx.x >> 3);
        int kk = by * 8  + (threadIdx.x & 7);

        int   g    = g_idx[kk * 8];
        int   qw   = qweight[(size_t)kk * N + n];
        int   qz   = qzeros[(size_t)g * (N / 8) + (n >> 3)];
        int   zero = ((qz >> ((n & 7) * 4)) & 15) + 1;
        float s    = scales[(size_t)g * N + n];

        __half h[8];
#pragma unroll
        for (int i = 0; i < 8; i++) {
            int w = ((qw >> (4 * i)) & 15) - zero;
            h[i] = __float2half(s * (float)w);
        }
        *(uint4*)&g_Wt[(size_t)n * K + kk * 8] = *(uint4*)h;
    }
}

// ---------------------------------------------------------------------------
// GEMM: C[M,N] = g_Xh[M,K] @ g_Wt[N,K]^T + bias.
// 128x128 CTA, BK=64, 3-stage cp.async, 128 threads = 4 warps (2x2),
// warp tile 64x64, raw mma.sync m16n8k16 + ldmatrix.x4, double-buffered
// fragments (LDSM of slice s+1 overlaps MMA of slice s).
// ---------------------------------------------------------------------------
__global__ __launch_bounds__(128, 2)
void gemm_kernel(const float* __restrict__ bias, float* __restrict__ C) {
    extern __shared__ __half smem[];
    const uint32_t sbase = smem_u32(smem);

    const int tid  = threadIdx.x;
    const int warp = tid >> 5;
    const int lane = tid & 31;
    const int wm   = (warp >> 1) * 64;   // warp M offset within CTA
    const int wn   = (warp & 1) * 64;    // warp N offset within CTA

    const int bm = blockIdx.y * BM;
    const int bn = blockIdx.x * BN;

    // ---- cp.async mapping: 2048 x 16B chunks/stage, 16 per thread ----
    const int r0 = tid >> 3;            // 0..15
    const int c0 = tid & 7;             // chunk in 128B data row
    const __half* gA = g_Xh + (size_t)(bm + r0) * K + c0 * 8;
    const __half* gB = g_Wt + (size_t)(bn + r0) * K + c0 * 8;
    const uint32_t dA = (uint32_t)(r0 * LDS_T + c0 * 8) * 2;
    const uint32_t dB = dA + A_HALFS * 2;

    // ---- ldmatrix lane address components (within a stage, in bytes) ----
    const uint32_t aRow = (uint32_t)(wm + (lane & 15));
    const uint32_t aColX = (uint32_t)((lane >> 4) * 8);
    const uint32_t aBase = sbase + (aRow * LDS_T + aColX) * 2;
    const uint32_t bRow = (uint32_t)(wn + (lane & 7) + ((lane >> 4) << 3));
    const uint32_t bColX = (uint32_t)(((lane >> 3) & 1) * 8);
    const uint32_t bBase = sbase + A_HALFS * 2 + (bRow * LDS_T + bColX) * 2;

    float acc[4][8][4];
#pragma unroll
    for (int i = 0; i < 4; i++)
#pragma unroll
        for (int j = 0; j < 8; j++)
#pragma unroll
            for (int t = 0; t < 4; t++)
                acc[i][j][t] = 0.0f;

    // ---- prologue: stages 0..1 ----
#pragma unroll
    for (int s = 0; s < STAGES - 1; s++) {
        const uint32_t st = sbase + (uint32_t)s * STAGE_BYTES;
        const size_t ko = (size_t)s * BK;
#pragma unroll
        for (int l = 0; l < 8; l++) {
            cp_async16(st + dA + l * 16 * LDS_T * 2, gA + (size_t)l * 16 * K + ko);
            cp_async16(st + dB + l * 16 * LDS_T * 2, gB + (size_t)l * 16 * K + ko);
        }
        cp_commit();
    }

    uint32_t a[2][4][4], b[2][4][4];

    for (int i = 0; i < NIT; i++) {
        cp_wait1();
        __syncthreads();

        const uint32_t so = (uint32_t)(i % STAGES) * STAGE_BYTES;

        // load k-slice 0 fragments (critical path) first
#pragma unroll
        for (int mi = 0; mi < 4; mi++)
            ldsm_x4(a[0][mi], aBase + so + (mi * 16 * LDS_T) * 2);
#pragma unroll
        for (int nj = 0; nj < 4; nj++)
            ldsm_x4(b[0][nj], bBase + so + (nj * 16 * LDS_T) * 2);

        // issue next-stage cp.async early (overlaps compute below)
        const int p = i + STAGES - 1;
        if (p < NIT) {
            const uint32_t st = sbase + (uint32_t)(p % STAGES) * STAGE_BYTES;
            const size_t ko = (size_t)p * BK;
#pragma unroll
            for (int l = 0; l < 8; l++) {
                cp_async16(st + dA + l * 16 * LDS_T * 2, gA + (size_t)l * 16 * K + ko);
                cp_async16(st + dB + l * 16 * LDS_T * 2, gB + (size_t)l * 16 * K + ko);
            }
        }
        cp_commit();

        // 4 k-slices, double-buffered frags
#pragma unroll
        for (int s = 0; s < 4; s++) {
            const int cur = s & 1, nxt = cur ^ 1;
            if (s < 3) {
                const uint32_t ks = (uint32_t)(s + 1) * 16 * 2;
#pragma unroll
                for (int mi = 0; mi < 4; mi++)
                    ldsm_x4(a[nxt][mi], aBase + so + (mi * 16 * LDS_T) * 2 + ks);
#pragma unroll
                for (int nj = 0; nj < 4; nj++)
                    ldsm_x4(b[nxt][nj], bBase + so + (nj * 16 * LDS_T) * 2 + ks);
            }
#pragma unroll
            for (int mi = 0; mi < 4; mi++) {
#pragma unroll
                for (int nj = 0; nj < 4; nj++) {
                    mma16816(acc[mi][nj * 2 + 0], a[cur][mi], &b[cur][nj][0]);
                    mma16816(acc[mi][nj * 2 + 1], a[cur][mi], &b[cur][nj][2]);
                }
            }
        }
    }
    cp_wait0();

    // ---- epilogue: direct register -> global, fused bias ----
    const int erow = lane >> 2;
    const int ecol = (lane & 3) * 2;
    float2 bb[8];
#pragma unroll
    for (int nj = 0; nj < 8; nj++)
        bb[nj] = *(const float2*)&bias[bn + wn + nj * 8 + ecol];

#pragma unroll
    for (int mi = 0; mi < 4; mi++) {
        const int gm0 = bm + wm + mi * 16 + erow;
#pragma unroll
        for (int nj = 0; nj < 8; nj++) {
            const int gn = bn + wn + nj * 8 + ecol;
            float2 v0, v1;
            v0.x = acc[mi][nj][0] + bb[nj].x;
            v0.y = acc[mi][nj][1] + bb[nj].y;
            v1.x = acc[mi][nj][2] + bb[nj].x;
            v1.y = acc[mi][nj][3] + bb[nj].y;
            *(float2*)&C[(size_t)gm0 * N + gn] = v0;
            *(float2*)&C[(size_t)(gm0 + 8) * N + gn] = v1;
        }
    }
}

// ---------------------------------------------------------------------------
extern "C" void kernel_launch(void* const* d_in, const int* in_sizes, int n_in,
                              void* d_out, int out_size) {
    const float* x       = (const float*)d_in[0];
    const int*   qweight = (const int*)d_in[1];
    const int*   qzeros  = (const int*)d_in[2];
    const float* scales  = (const float*)d_in[3];
    const int*   g_idx   = (const int*)d_in[4];
    const float* bias    = (const float*)d_in[5];
    float*       out     = (float*)d_out;

    cudaFuncSetAttribute(gemm_kernel,
                         cudaFuncAttributeMaxDynamicSharedMemorySize, SMEM_BYTES);

    int prep_blocks = CONV_BLOCKS + (N / 32) * (KP / 8);
    prep_kernel<<<prep_blocks, 256>>>(x, qweight, qzeros, scales, g_idx);

    dim3 gemm_grid(N / BN, M / BM);   // 86 x 32
    gemm_kernel<<<gemm_grid, 128, SMEM_BYTES>>>(bias, out);
}